// round 5
// baseline (speedup 1.0000x reference)
#include <cuda_runtime.h>
#include <math.h>

#define NN   50000
#define EE   640000
#define HD   128
#define NH   8
#define CC   16
#define LL   3
#define EFD  16

typedef unsigned long long ull;

// ---------------- scratch (static device globals) ---------------------------
__device__ __align__(256) float g_xl   [(size_t)NN * HD];
__device__ __align__(256) float g_xr   [(size_t)NN * HD];
__device__ __align__(256) float g_denom[(size_t)NN * NH];
__device__ __align__(256) float g_agg  [(size_t)NN * HD];
__device__ __align__(256) float g_Wf   [LL][EFD * HD];   // Wt @ We[l]
__device__ __align__(256) float g_bf   [LL][HD];         // bt @ We[l]

// ---------------- helpers ---------------------------------------------------
__device__ __forceinline__ ull bcast2(float x) {
    ull r; asm("mov.b64 %0, {%1, %1};" : "=l"(r) : "f"(x)); return r;
}
__device__ __forceinline__ ull pack2(float lo, float hi) {
    ull r; asm("mov.b64 %0, {%1, %2};" : "=l"(r) : "f"(lo), "f"(hi)); return r;
}
__device__ __forceinline__ void fma2(ull& acc, ull a, ull b) {
    asm("fma.rn.f32x2 %0, %1, %2, %0;" : "+l"(acc) : "l"(a), "l"(b));
}
__device__ __forceinline__ void unpack2(ull v, float& lo, float& hi) {
    asm("mov.b64 {%0, %1}, %2;" : "=f"(lo), "=f"(hi) : "l"(v));
}
__device__ __forceinline__ float lrelu(float x) { return fmaxf(x, 0.2f * x); }

// ---------------- kernels ---------------------------------------------------

// Fold edge_transform into each layer's lin_edge:
//   Wf[l] = Wt @ We[l]  [16,128];  bf[l] = bt @ We[l]  [128]
__global__ void fusew_kernel(const float* __restrict__ Wt,
                             const float* __restrict__ bt,
                             const float* __restrict__ We) {
    int l = blockIdx.x;
    int j = threadIdx.x;
    const float* We_l = We + (size_t)l * HD * HD;
    float b = 0.f;
    for (int m = 0; m < HD; m++) b = fmaf(bt[m], We_l[m * HD + j], b);
    g_bf[l][j] = b;
    #pragma unroll
    for (int k = 0; k < EFD; k++) {
        float s = 0.f;
        for (int m = 0; m < HD; m++) s = fmaf(Wt[k * HD + m], We_l[m * HD + j], s);
        g_Wf[l][k * HD + j] = s;
    }
}

// xl = x@Wl + bl, xr = x@Wr + br in one launch. 8 rows/block, 256 threads.
__global__ void __launch_bounds__(256)
node_gemm_kernel(const float* __restrict__ x,
                 const float* __restrict__ Wl_l, const float* __restrict__ bl_l,
                 const float* __restrict__ Wr_l, const float* __restrict__ br_l) {
    __shared__ float AsT[HD][8];         // [k][row]
    int row0 = blockIdx.x * 8;
    for (int i = threadIdx.x; i < 8 * HD; i += 256) {
        int r = i >> 7, c = i & 127;
        AsT[c][r] = x[(size_t)(row0 + r) * HD + c];
    }
    __syncthreads();

    int half = threadIdx.x >> 7;         // 0 -> lin_l, 1 -> lin_r
    int t    = threadIdx.x & 127;
    const float* W    = half ? Wr_l : Wl_l;
    const float* bias = half ? br_l : bl_l;
    float* C          = half ? g_xr : g_xl;

    int p  = t & 63;                     // column pair (2p, 2p+1)
    int rb = (t >> 6) * 4;               // rows rb..rb+3

    ull acc[4] = {0ull, 0ull, 0ull, 0ull};
    const ull* W2 = (const ull*)W;

    #pragma unroll 8
    for (int k = 0; k < HD; k++) {
        float4 a = *(const float4*)&AsT[k][rb];
        ull a01 = pack2(a.x, a.y);
        ull a23 = pack2(a.z, a.w);
        ull w = W2[k * 64 + p];
        float wlo, whi; unpack2(w, wlo, whi);
        ull wl2 = bcast2(wlo), wh2 = bcast2(whi);
        fma2(acc[0], a01, wl2);  fma2(acc[1], a23, wl2);
        fma2(acc[2], a01, wh2);  fma2(acc[3], a23, wh2);
    }
    float blo = bias[2 * p], bhi = bias[2 * p + 1];
    float f0, f1;
    unpack2(acc[0], f0, f1);
    C[(size_t)(row0 + rb + 0) * HD + 2 * p] = f0 + blo;
    C[(size_t)(row0 + rb + 1) * HD + 2 * p] = f1 + blo;
    unpack2(acc[1], f0, f1);
    C[(size_t)(row0 + rb + 2) * HD + 2 * p] = f0 + blo;
    C[(size_t)(row0 + rb + 3) * HD + 2 * p] = f1 + blo;
    unpack2(acc[2], f0, f1);
    C[(size_t)(row0 + rb + 0) * HD + 2 * p + 1] = f0 + bhi;
    C[(size_t)(row0 + rb + 1) * HD + 2 * p + 1] = f1 + bhi;
    unpack2(acc[3], f0, f1);
    C[(size_t)(row0 + rb + 2) * HD + 2 * p + 1] = f0 + bhi;
    C[(size_t)(row0 + rb + 3) * HD + 2 * p + 1] = f1 + bhi;
}

// one-time zero of the accumulators (before layer 0)
__global__ void zero_kernel() {
    int i = blockIdx.x * blockDim.x + threadIdx.x;
    if (i < NN * HD) g_agg[i] = 0.f;
    if (i < NN * NH) g_denom[i] = 0.f;
}

// Fully fused edge pass, 8 lanes per edge (one head per lane, 4 edges/warp):
// em on-the-fly (packed f32x2 FMA from smem Wf, bank-conflict-free rotated
// access), lane-private logit dot, exp, denom atomic, unnormalized weighted
// scatter of xl[src]. Normalization deferred to node_finish.
__global__ void __launch_bounds__(512, 2)
edge_p_kernel(const int* __restrict__ src, const int* __restrict__ dst,
              const float* __restrict__ eattr, const float* __restrict__ att_l,
              const float* __restrict__ Wf_l, const float* __restrict__ bf_l) {
    __shared__ float Wfs[EFD * HD];   // 8KB
    __shared__ float bfs[HD];
    __shared__ float atts[NH * CC];
    for (int i = threadIdx.x; i < EFD * HD; i += 512) Wfs[i] = Wf_l[i];
    if (threadIdx.x < HD) {
        bfs[threadIdx.x]  = bf_l[threadIdx.x];
        atts[threadIdx.x] = att_l[threadIdx.x];
    }
    __syncthreads();

    int e   = blockIdx.x * 64 + (threadIdx.x >> 3);
    int sub = threadIdx.x & 7;            // head index; channels sub*16..+15
    int s = src[e], d = dst[e];
    int cbase = sub * CC;

    // rotated chunk order: lane handles chunks jj(j) = ((sub>>1)+j)&3
    int jj0 = (sub >> 1) & 3;

    // edge attrs (8-lane broadcast loads)
    const float4* ea4 = (const float4*)(eattr + (size_t)e * EFD);
    float4 e0 = ea4[0], e1 = ea4[1], e2 = ea4[2], e3 = ea4[3];
    float ea16[16] = {e0.x, e0.y, e0.z, e0.w, e1.x, e1.y, e1.z, e1.w,
                      e2.x, e2.y, e2.z, e2.w, e3.x, e3.y, e3.z, e3.w};

    // em accumulators: em2[jj*2], em2[jj*2+1] hold channels cbase+jj*4 .. +3
    ull em2[8];
    #pragma unroll
    for (int j = 0; j < 4; j++) {
        int jj = (jj0 + j) & 3;
        const ulonglong2* b2 = (const ulonglong2*)&bfs[cbase + jj * 4];
        ulonglong2 bv = *b2;
        em2[jj * 2]     = bv.x;
        em2[jj * 2 + 1] = bv.y;
    }

    #pragma unroll
    for (int k = 0; k < EFD; k++) {
        ull a2 = bcast2(ea16[k]);
        const float* wrow = &Wfs[k * HD + cbase];
        #pragma unroll
        for (int j = 0; j < 4; j++) {
            int jj = (jj0 + j) & 3;
            ulonglong2 w = *(const ulonglong2*)&wrow[jj * 4];
            fma2(em2[jj * 2],     a2, w.x);
            fma2(em2[jj * 2 + 1], a2, w.y);
        }
    }

    // gather xl/xr, finish logit; keep xl for the scatter
    float logit = 0.f;
    float4 xlv[4];
    #pragma unroll
    for (int j = 0; j < 4; j++) {
        int jj = (jj0 + j) & 3;
        float4 xa = *(const float4*)&g_xl[(size_t)s * HD + cbase + jj * 4];
        float4 xb = *(const float4*)&g_xr[(size_t)d * HD + cbase + jj * 4];
        float4 at = *(const float4*)&atts[cbase + jj * 4];
        float m0, m1, m2, m3, t0, t1;
        unpack2(em2[jj * 2],     m0, m1);
        unpack2(em2[jj * 2 + 1], m2, m3);
        t0 = lrelu(xa.x + xb.x + m0) * at.x;
        t1 = lrelu(xa.y + xb.y + m1) * at.y;
        t0 = fmaf(at.z, lrelu(xa.z + xb.z + m2), t0);
        t1 = fmaf(at.w, lrelu(xa.w + xb.w + m3), t1);
        logit += t0 + t1;
        xlv[jj] = xa;
    }

    float pv = expf(logit);               // softmax is shift-invariant
    atomicAdd(&g_denom[(size_t)d * NH + sub], pv);
    #pragma unroll
    for (int j = 0; j < 4; j++) {
        int jj = (jj0 + j) & 3;
        float4 v = xlv[jj];
        v.x *= pv; v.y *= pv; v.z *= pv; v.w *= pv;
        atomicAdd((float4*)&g_agg[(size_t)d * HD + cbase + jj * 4], v);
    }
}

// x = relu(LN(agg/denom + bias_o)) + x ; also re-zeroes agg/denom for the
// next layer (one warp per node).
__global__ void __launch_bounds__(256)
node_finish_kernel(const float* __restrict__ bo_l,
                   const float* __restrict__ lg_l,
                   const float* __restrict__ lb_l,
                   float* __restrict__ x) {
    int n = blockIdx.x * 8 + (threadIdx.x >> 5);
    if (n >= NN) return;
    int lane = threadIdx.x & 31;
    int h = lane >> 2;

    float den = g_denom[(size_t)n * NH + h] + 1e-16f;
    float rden = 1.f / den;

    float4 v  = *(const float4*)&g_agg[(size_t)n * HD + lane * 4];
    float4 bo = *(const float4*)&bo_l[lane * 4];
    v.x = fmaf(v.x, rden, bo.x); v.y = fmaf(v.y, rden, bo.y);
    v.z = fmaf(v.z, rden, bo.z); v.w = fmaf(v.w, rden, bo.w);

    // zero accumulators for next layer
    *(float4*)&g_agg[(size_t)n * HD + lane * 4] = make_float4(0.f, 0.f, 0.f, 0.f);
    if ((lane & 3) == 0) g_denom[(size_t)n * NH + h] = 0.f;

    float s  = v.x + v.y + v.z + v.w;
    float sq = v.x * v.x + v.y * v.y + v.z * v.z + v.w * v.w;
    #pragma unroll
    for (int o = 16; o > 0; o >>= 1) {
        s  += __shfl_xor_sync(0xffffffffu, s,  o);
        sq += __shfl_xor_sync(0xffffffffu, sq, o);
    }
    float mu  = s * (1.f / HD);
    float var = sq * (1.f / HD) - mu * mu;
    float inv = rsqrtf(var + 1e-5f);

    float4 g  = *(const float4*)&lg_l[lane * 4];
    float4 bb = *(const float4*)&lb_l[lane * 4];
    float4 xi = *(const float4*)&x[(size_t)n * HD + lane * 4];

    float4 o;
    o.x = fmaxf(g.x * (v.x - mu) * inv + bb.x, 0.f) + xi.x;
    o.y = fmaxf(g.y * (v.y - mu) * inv + bb.y, 0.f) + xi.y;
    o.z = fmaxf(g.z * (v.z - mu) * inv + bb.z, 0.f) + xi.z;
    o.w = fmaxf(g.w * (v.w - mu) * inv + bb.w, 0.f) + xi.w;
    *(float4*)&x[(size_t)n * HD + lane * 4] = o;
}

// ---------------- host ------------------------------------------------------
extern "C" void kernel_launch(void* const* d_in, const int* in_sizes, int n_in,
                              void* d_out, int out_size) {
    const float* x_in   = (const float*)d_in[0];
    const int*   eidx   = (const int*)  d_in[2];
    const float* eattr  = (const float*)d_in[3];
    const float* Wt     = (const float*)d_in[4];
    const float* bt     = (const float*)d_in[5];
    const float* Wl     = (const float*)d_in[6];
    const float* bl     = (const float*)d_in[7];
    const float* Wr     = (const float*)d_in[8];
    const float* br     = (const float*)d_in[9];
    const float* We     = (const float*)d_in[10];
    const float* att    = (const float*)d_in[11];
    const float* bias_o = (const float*)d_in[12];
    const float* ln_g   = (const float*)d_in[13];
    const float* ln_b   = (const float*)d_in[14];
    float* x = (float*)d_out;

    const int* src = eidx;
    const int* dst = eidx + EE;

    float *p_Wf, *p_bf;
    cudaGetSymbolAddress((void**)&p_Wf, g_Wf);
    cudaGetSymbolAddress((void**)&p_bf, g_bf);

    cudaMemcpyAsync(x, x_in, (size_t)NN * HD * sizeof(float),
                    cudaMemcpyDeviceToDevice);

    fusew_kernel<<<LL, HD>>>(Wt, bt, We);
    zero_kernel<<<(NN * HD + 255) / 256, 256>>>();

    for (int l = 0; l < LL; l++) {
        node_gemm_kernel<<<NN / 8, 256>>>(x,
                                          Wl + (size_t)l * HD * HD, bl + l * HD,
                                          Wr + (size_t)l * HD * HD, br + l * HD);
        edge_p_kernel<<<EE / 64, 512>>>(src, dst, eattr, att + l * NH * CC,
                                        p_Wf + (size_t)l * EFD * HD,
                                        p_bf + (size_t)l * HD);
        node_finish_kernel<<<NN / 8 + 1, 256>>>(bias_o + l * HD,
                                                ln_g + l * HD,
                                                ln_b + l * HD, x);
    }
}

// round 9
// speedup vs baseline: 6.9606x; 6.9606x over previous
#include <cuda_runtime.h>
#include <math.h>

#define NN   50000
#define EE   640000
#define HD   128
#define NH   8
#define CC   16
#define LL   3
#define EFD  16

typedef unsigned long long ull;

// ---------------- scratch (static device globals) ---------------------------
__device__ __align__(256) float g_xl   [(size_t)NN * HD];
__device__ __align__(256) float g_xr   [(size_t)NN * HD];
__device__ __align__(256) float g_denom[(size_t)NN * NH];
__device__ __align__(256) float g_agg  [(size_t)NN * HD];
__device__ __align__(256) float g_Wf   [LL][EFD * HD];   // Wt @ We[l]
__device__ __align__(256) float g_bf   [LL][HD];         // bt @ We[l]

// ---------------- helpers ---------------------------------------------------
__device__ __forceinline__ ull bcast2(float x) {
    ull r; asm("mov.b64 %0, {%1, %1};" : "=l"(r) : "f"(x)); return r;
}
__device__ __forceinline__ ull pack2(float lo, float hi) {
    ull r; asm("mov.b64 %0, {%1, %2};" : "=l"(r) : "f"(lo), "f"(hi)); return r;
}
__device__ __forceinline__ void fma2(ull& acc, ull a, ull b) {
    asm("fma.rn.f32x2 %0, %1, %2, %0;" : "+l"(acc) : "l"(a), "l"(b));
}
__device__ __forceinline__ void unpack2(ull v, float& lo, float& hi) {
    asm("mov.b64 {%0, %1}, %2;" : "=f"(lo), "=f"(hi) : "l"(v));
}
__device__ __forceinline__ float lrelu(float x) { return fmaxf(x, 0.2f * x); }

// ---------------- kernels ---------------------------------------------------

// Fold edge_transform into each layer's lin_edge:
//   Wf[l] = Wt @ We[l]  [16,128];  bf[l] = bt @ We[l]  [128]
__global__ void fusew_kernel(const float* __restrict__ Wt,
                             const float* __restrict__ bt,
                             const float* __restrict__ We) {
    int l = blockIdx.x;
    int j = threadIdx.x;
    const float* We_l = We + (size_t)l * HD * HD;
    float b = 0.f;
    for (int m = 0; m < HD; m++) b = fmaf(bt[m], We_l[m * HD + j], b);
    g_bf[l][j] = b;
    #pragma unroll
    for (int k = 0; k < EFD; k++) {
        float s = 0.f;
        for (int m = 0; m < HD; m++) s = fmaf(Wt[k * HD + m], We_l[m * HD + j], s);
        g_Wf[l][k * HD + j] = s;
    }
}

// xl = x@Wl + bl, xr = x@Wr + br in one launch. 16 rows/block, 256 threads
// (half does Wl, half Wr). Per-thread: 8 rows x 2 cols.
__global__ void __launch_bounds__(256)
node_gemm_kernel(const float* __restrict__ x,
                 const float* __restrict__ Wl_l, const float* __restrict__ bl_l,
                 const float* __restrict__ Wr_l, const float* __restrict__ br_l) {
    __shared__ float AsT[HD][16];        // [k][row]
    int row0 = blockIdx.x * 16;
    for (int i = threadIdx.x; i < 16 * HD; i += 256) {
        int r = i >> 7, c = i & 127;
        AsT[c][r] = x[(size_t)(row0 + r) * HD + c];
    }
    __syncthreads();

    int half = threadIdx.x >> 7;         // 0 -> lin_l, 1 -> lin_r
    int t    = threadIdx.x & 127;
    const float* W    = half ? Wr_l : Wl_l;
    const float* bias = half ? br_l : bl_l;
    float* C          = half ? g_xr : g_xl;

    int p  = t & 63;                     // column pair (2p, 2p+1)
    int rb = (t >> 6) * 8;               // rows rb..rb+7

    ull acc[8] = {0ull,0ull,0ull,0ull,0ull,0ull,0ull,0ull};
    const ull* W2 = (const ull*)W;

    #pragma unroll 4
    for (int k = 0; k < HD; k++) {
        float4 a0 = *(const float4*)&AsT[k][rb];        // rows rb..rb+3
        float4 a1 = *(const float4*)&AsT[k][rb + 4];    // rows rb+4..rb+7
        ull a01 = pack2(a0.x, a0.y), a23 = pack2(a0.z, a0.w);
        ull a45 = pack2(a1.x, a1.y), a67 = pack2(a1.z, a1.w);
        ull w = W2[k * 64 + p];
        float wlo, whi; unpack2(w, wlo, whi);
        ull wl2 = bcast2(wlo), wh2 = bcast2(whi);
        fma2(acc[0], a01, wl2);  fma2(acc[1], a23, wl2);
        fma2(acc[2], a45, wl2);  fma2(acc[3], a67, wl2);
        fma2(acc[4], a01, wh2);  fma2(acc[5], a23, wh2);
        fma2(acc[6], a45, wh2);  fma2(acc[7], a67, wh2);
    }
    float blo = bias[2 * p], bhi = bias[2 * p + 1];
    #pragma unroll
    for (int g = 0; g < 4; g++) {
        float f0, f1;
        unpack2(acc[g], f0, f1);
        C[(size_t)(row0 + rb + 2 * g + 0) * HD + 2 * p] = f0 + blo;
        C[(size_t)(row0 + rb + 2 * g + 1) * HD + 2 * p] = f1 + blo;
        unpack2(acc[4 + g], f0, f1);
        C[(size_t)(row0 + rb + 2 * g + 0) * HD + 2 * p + 1] = f0 + bhi;
        C[(size_t)(row0 + rb + 2 * g + 1) * HD + 2 * p + 1] = f1 + bhi;
    }
}

// one-time zero of the accumulators (before layer 0)
__global__ void zero_kernel() {
    int i = blockIdx.x * blockDim.x + threadIdx.x;
    if (i < NN * HD) g_agg[i] = 0.f;
    if (i < NN * NH) g_denom[i] = 0.f;
}

// Fully fused edge pass (one warp per edge): em on-the-fly from folded
// weights -> logit -> exp -> denom atomic + unnormalized weighted scatter.
// 512-thread blocks so 3 blocks/SM fit (occupancy was the R4 limiter).
__global__ void __launch_bounds__(512)
edge_p_kernel(const int* __restrict__ src, const int* __restrict__ dst,
              const float* __restrict__ eattr, const float* __restrict__ att_l,
              const float* __restrict__ Wf_l, const float* __restrict__ bf_l) {
    __shared__ float Wfs[EFD * HD];
    __shared__ float bfs[HD];
    for (int i = threadIdx.x; i < EFD * HD; i += 512) Wfs[i] = Wf_l[i];
    if (threadIdx.x < HD) bfs[threadIdx.x] = bf_l[threadIdx.x];
    __syncthreads();

    int e = blockIdx.x * 16 + (threadIdx.x >> 5);
    int lane = threadIdx.x & 31;
    int s = src[e], d = dst[e];
    int h = lane >> 2;
    int c = lane * 4;

    const float4* ea4 = (const float4*)(eattr + (size_t)e * EFD);
    float4 e0 = ea4[0], e1 = ea4[1], e2 = ea4[2], e3 = ea4[3];
    float ea16[16] = {e0.x, e0.y, e0.z, e0.w, e1.x, e1.y, e1.z, e1.w,
                      e2.x, e2.y, e2.z, e2.w, e3.x, e3.y, e3.z, e3.w};

    float4 em = *(const float4*)&bfs[c];
    #pragma unroll
    for (int k = 0; k < EFD; k++) {
        float4 w = *(const float4*)&Wfs[k * HD + c];
        float a = ea16[k];
        em.x = fmaf(a, w.x, em.x); em.y = fmaf(a, w.y, em.y);
        em.z = fmaf(a, w.z, em.z); em.w = fmaf(a, w.w, em.w);
    }

    float4 a  = *(const float4*)&g_xl[(size_t)s * HD + c];
    float4 b  = *(const float4*)&g_xr[(size_t)d * HD + c];
    float4 at = *(const float4*)&att_l[h * CC + (lane & 3) * 4];

    float sum = lrelu(a.x + b.x + em.x) * at.x
              + lrelu(a.y + b.y + em.y) * at.y
              + lrelu(a.z + b.z + em.z) * at.z
              + lrelu(a.w + b.w + em.w) * at.w;
    sum += __shfl_xor_sync(0xffffffffu, sum, 1);
    sum += __shfl_xor_sync(0xffffffffu, sum, 2);
    // all 4 lanes of the quad hold the full per-head logit
    float pv = expf(sum);                   // softmax is shift-invariant
    if ((lane & 3) == 0)
        atomicAdd(&g_denom[(size_t)d * NH + h], pv);
    a.x *= pv; a.y *= pv; a.z *= pv; a.w *= pv;   // xl[src] already in regs
    atomicAdd((float4*)&g_agg[(size_t)d * HD + c], a);
}

// x = relu(LN(agg/denom + bias_o)) + x ; re-zeroes agg/denom for next layer.
__global__ void __launch_bounds__(256)
node_finish_kernel(const float* __restrict__ bo_l,
                   const float* __restrict__ lg_l,
                   const float* __restrict__ lb_l,
                   float* __restrict__ x) {
    int n = blockIdx.x * 8 + (threadIdx.x >> 5);
    if (n >= NN) return;
    int lane = threadIdx.x & 31;
    int h = lane >> 2;

    float den = g_denom[(size_t)n * NH + h] + 1e-16f;
    float rden = 1.f / den;

    float4 v  = *(const float4*)&g_agg[(size_t)n * HD + lane * 4];
    float4 bo = *(const float4*)&bo_l[lane * 4];
    v.x = fmaf(v.x, rden, bo.x); v.y = fmaf(v.y, rden, bo.y);
    v.z = fmaf(v.z, rden, bo.z); v.w = fmaf(v.w, rden, bo.w);

    *(float4*)&g_agg[(size_t)n * HD + lane * 4] = make_float4(0.f, 0.f, 0.f, 0.f);
    if ((lane & 3) == 0) g_denom[(size_t)n * NH + h] = 0.f;

    float s  = v.x + v.y + v.z + v.w;
    float sq = v.x * v.x + v.y * v.y + v.z * v.z + v.w * v.w;
    #pragma unroll
    for (int o = 16; o > 0; o >>= 1) {
        s  += __shfl_xor_sync(0xffffffffu, s,  o);
        sq += __shfl_xor_sync(0xffffffffu, sq, o);
    }
    float mu  = s * (1.f / HD);
    float var = sq * (1.f / HD) - mu * mu;
    float inv = rsqrtf(var + 1e-5f);

    float4 g  = *(const float4*)&lg_l[lane * 4];
    float4 bb = *(const float4*)&lb_l[lane * 4];
    float4 xi = *(const float4*)&x[(size_t)n * HD + lane * 4];

    float4 o;
    o.x = fmaxf(g.x * (v.x - mu) * inv + bb.x, 0.f) + xi.x;
    o.y = fmaxf(g.y * (v.y - mu) * inv + bb.y, 0.f) + xi.y;
    o.z = fmaxf(g.z * (v.z - mu) * inv + bb.z, 0.f) + xi.z;
    o.w = fmaxf(g.w * (v.w - mu) * inv + bb.w, 0.f) + xi.w;
    *(float4*)&x[(size_t)n * HD + lane * 4] = o;
}

// ---------------- host ------------------------------------------------------
extern "C" void kernel_launch(void* const* d_in, const int* in_sizes, int n_in,
                              void* d_out, int out_size) {
    const float* x_in   = (const float*)d_in[0];
    const int*   eidx   = (const int*)  d_in[2];
    const float* eattr  = (const float*)d_in[3];
    const float* Wt     = (const float*)d_in[4];
    const float* bt     = (const float*)d_in[5];
    const float* Wl     = (const float*)d_in[6];
    const float* bl     = (const float*)d_in[7];
    const float* Wr     = (const float*)d_in[8];
    const float* br     = (const float*)d_in[9];
    const float* We     = (const float*)d_in[10];
    const float* att    = (const float*)d_in[11];
    const float* bias_o = (const float*)d_in[12];
    const float* ln_g   = (const float*)d_in[13];
    const float* ln_b   = (const float*)d_in[14];
    float* x = (float*)d_out;

    const int* src = eidx;
    const int* dst = eidx + EE;

    float *p_Wf, *p_bf;
    cudaGetSymbolAddress((void**)&p_Wf, g_Wf);
    cudaGetSymbolAddress((void**)&p_bf, g_bf);

    cudaMemcpyAsync(x, x_in, (size_t)NN * HD * sizeof(float),
                    cudaMemcpyDeviceToDevice);

    fusew_kernel<<<LL, HD>>>(Wt, bt, We);
    zero_kernel<<<(NN * HD + 255) / 256, 256>>>();

    for (int l = 0; l < LL; l++) {
        node_gemm_kernel<<<NN / 16 + 1, 256>>>(x,
                                          Wl + (size_t)l * HD * HD, bl + l * HD,
                                          Wr + (size_t)l * HD * HD, br + l * HD);
        edge_p_kernel<<<EE / 16, 512>>>(src, dst, eattr, att + l * NH * CC,
                                        p_Wf + (size_t)l * EFD * HD,
                                        p_bf + (size_t)l * HD);
        node_finish_kernel<<<NN / 8 + 1, 256>>>(bias_o + l * HD,
                                                ln_g + l * HD,
                                                ln_b + l * HD, x);
    }
}

// round 10
// speedup vs baseline: 9.4621x; 1.3594x over previous
#include <cuda_runtime.h>
#include <math.h>

#define NN   50000
#define EE   640000
#define HD   128
#define NH   8
#define CC   16
#define LL   3
#define EFD  16

typedef unsigned long long ull;

// ---------------- scratch (static device globals) ---------------------------
__device__ __align__(256) float g_xl   [(size_t)NN * HD];
__device__ __align__(256) float g_xr   [(size_t)NN * HD];
__device__ __align__(256) float g_denom[(size_t)NN * NH];
__device__ __align__(256) float g_agg  [(size_t)NN * HD];
__device__ __align__(256) float g_Wf   [LL][EFD * HD];   // Wt @ We[l]
__device__ __align__(256) float g_bf   [LL][HD];         // bt @ We[l]

// ---------------- helpers ---------------------------------------------------
__device__ __forceinline__ ull bcast2(float x) {
    ull r; asm("mov.b64 %0, {%1, %1};" : "=l"(r) : "f"(x)); return r;
}
__device__ __forceinline__ ull pack2(float lo, float hi) {
    ull r; asm("mov.b64 %0, {%1, %2};" : "=l"(r) : "f"(lo), "f"(hi)); return r;
}
__device__ __forceinline__ void fma2(ull& acc, ull a, ull b) {
    asm("fma.rn.f32x2 %0, %1, %2, %0;" : "+l"(acc) : "l"(a), "l"(b));
}
__device__ __forceinline__ void unpack2(ull v, float& lo, float& hi) {
    asm("mov.b64 {%0, %1}, %2;" : "=f"(lo), "=f"(hi) : "l"(v));
}
__device__ __forceinline__ float lrelu(float x) { return fmaxf(x, 0.2f * x); }

// ---------------- kernels ---------------------------------------------------

// Fold edge_transform into each layer's lin_edge:
//   Wf[l] = Wt @ We[l]  [16,128];  bf[l] = bt @ We[l]  [128]
__global__ void fusew_kernel(const float* __restrict__ Wt,
                             const float* __restrict__ bt,
                             const float* __restrict__ We) {
    int l = blockIdx.x;
    int j = threadIdx.x;
    const float* We_l = We + (size_t)l * HD * HD;
    float b = 0.f;
    for (int m = 0; m < HD; m++) b = fmaf(bt[m], We_l[m * HD + j], b);
    g_bf[l][j] = b;
    #pragma unroll
    for (int k = 0; k < EFD; k++) {
        float s = 0.f;
        for (int m = 0; m < HD; m++) s = fmaf(Wt[k * HD + m], We_l[m * HD + j], s);
        g_Wf[l][k * HD + j] = s;
    }
}

// xl = x@Wl + bl, xr = x@Wr + br in one launch. 16 rows/block, 256 threads
// (half does Wl, half Wr). Per-thread: 8 rows x 2 cols.
__global__ void __launch_bounds__(256)
node_gemm_kernel(const float* __restrict__ x,
                 const float* __restrict__ Wl_l, const float* __restrict__ bl_l,
                 const float* __restrict__ Wr_l, const float* __restrict__ br_l) {
    __shared__ float AsT[HD][16];        // [k][row]
    int row0 = blockIdx.x * 16;
    for (int i = threadIdx.x; i < 16 * HD; i += 256) {
        int r = i >> 7, c = i & 127;
        AsT[c][r] = x[(size_t)(row0 + r) * HD + c];
    }
    __syncthreads();

    int half = threadIdx.x >> 7;         // 0 -> lin_l, 1 -> lin_r
    int t    = threadIdx.x & 127;
    const float* W    = half ? Wr_l : Wl_l;
    const float* bias = half ? br_l : bl_l;
    float* C          = half ? g_xr : g_xl;

    int p  = t & 63;                     // column pair (2p, 2p+1)
    int rb = (t >> 6) * 8;               // rows rb..rb+7

    ull acc[8] = {0ull,0ull,0ull,0ull,0ull,0ull,0ull,0ull};
    const ull* W2 = (const ull*)W;

    #pragma unroll 4
    for (int k = 0; k < HD; k++) {
        float4 a0 = *(const float4*)&AsT[k][rb];
        float4 a1 = *(const float4*)&AsT[k][rb + 4];
        ull a01 = pack2(a0.x, a0.y), a23 = pack2(a0.z, a0.w);
        ull a45 = pack2(a1.x, a1.y), a67 = pack2(a1.z, a1.w);
        ull w = W2[k * 64 + p];
        float wlo, whi; unpack2(w, wlo, whi);
        ull wl2 = bcast2(wlo), wh2 = bcast2(whi);
        fma2(acc[0], a01, wl2);  fma2(acc[1], a23, wl2);
        fma2(acc[2], a45, wl2);  fma2(acc[3], a67, wl2);
        fma2(acc[4], a01, wh2);  fma2(acc[5], a23, wh2);
        fma2(acc[6], a45, wh2);  fma2(acc[7], a67, wh2);
    }
    float blo = bias[2 * p], bhi = bias[2 * p + 1];
    #pragma unroll
    for (int g = 0; g < 4; g++) {
        float f0, f1;
        unpack2(acc[g], f0, f1);
        C[(size_t)(row0 + rb + 2 * g + 0) * HD + 2 * p] = f0 + blo;
        C[(size_t)(row0 + rb + 2 * g + 1) * HD + 2 * p] = f1 + blo;
        unpack2(acc[4 + g], f0, f1);
        C[(size_t)(row0 + rb + 2 * g + 0) * HD + 2 * p + 1] = f0 + bhi;
        C[(size_t)(row0 + rb + 2 * g + 1) * HD + 2 * p + 1] = f1 + bhi;
    }
}

// one-time zero of the accumulators (before layer 0)
__global__ void zero_kernel() {
    int i = blockIdx.x * blockDim.x + threadIdx.x;
    if (i < NN * HD) g_agg[i] = 0.f;
    if (i < NN * NH) g_denom[i] = 0.f;
}

// Fused edge pass, 4 edges per warp: the Wf smem row is loaded ONCE per
// k-step and applied to all 4 edges (ea scalars broadcast via static-index
// register shuffles). This cuts the dominant smem wavefront traffic 4x
// (R9 ncu: L1=96.2% with 64 LDS wavefronts/edge from Wf re-reads).
__global__ void __launch_bounds__(512)
edge_p_kernel(const int* __restrict__ src, const int* __restrict__ dst,
              const float* __restrict__ eattr, const float* __restrict__ att_l,
              const float* __restrict__ Wf_l, const float* __restrict__ bf_l) {
    __shared__ float Wfs[EFD * HD];
    __shared__ float bfs[HD];
    __shared__ float atts[NH * CC];
    for (int i = threadIdx.x; i < EFD * HD; i += 512) Wfs[i] = Wf_l[i];
    if (threadIdx.x < HD) {
        bfs[threadIdx.x]  = bf_l[threadIdx.x];
        atts[threadIdx.x] = att_l[threadIdx.x];
    }
    __syncthreads();

    int warp = threadIdx.x >> 5;
    int lane = threadIdx.x & 31;
    int e0   = blockIdx.x * 64 + warp * 4;      // 4 consecutive edges
    int h = lane >> 2;
    int c = lane * 4;

    // 4 edges x 16 attrs = 64 floats, distributed 2 per lane (coalesced 128B)
    float ea_a = eattr[(size_t)e0 * EFD + lane];        // values 0..31
    float ea_b = eattr[(size_t)e0 * EFD + 32 + lane];   // values 32..63

    // em accumulators: em[g][0] = channels c,c+1 ; em[g][1] = c+2,c+3
    ull em[4][2];
    {
        ulonglong2 bv = *(const ulonglong2*)&bfs[c];
        #pragma unroll
        for (int g = 0; g < 4; g++) { em[g][0] = bv.x; em[g][1] = bv.y; }
    }

    #pragma unroll
    for (int k = 0; k < EFD; k++) {
        float4 w = *(const float4*)&Wfs[k * HD + c];    // shared by 4 edges
        ull wxy = pack2(w.x, w.y), wzw = pack2(w.z, w.w);
        #pragma unroll
        for (int g = 0; g < 4; g++) {
            int v = g * EFD + k;                        // compile-time
            float a = __shfl_sync(0xffffffffu,
                                  (v < 32) ? ea_a : ea_b, v & 31);
            ull a2 = bcast2(a);
            fma2(em[g][0], a2, wxy);
            fma2(em[g][1], a2, wzw);
        }
    }

    int4 s4 = *(const int4*)&src[e0];
    int4 d4 = *(const int4*)&dst[e0];
    int ss[4] = {s4.x, s4.y, s4.z, s4.w};
    int dd[4] = {d4.x, d4.y, d4.z, d4.w};

    float4 at = *(const float4*)&atts[h * CC + (lane & 3) * 4];

    #pragma unroll
    for (int g = 0; g < 4; g++) {
        int s = ss[g], d = dd[g];
        float4 xa = *(const float4*)&g_xl[(size_t)s * HD + c];
        float4 xb = *(const float4*)&g_xr[(size_t)d * HD + c];
        float m0, m1, m2, m3;
        unpack2(em[g][0], m0, m1);
        unpack2(em[g][1], m2, m3);

        float sum = lrelu(xa.x + xb.x + m0) * at.x
                  + lrelu(xa.y + xb.y + m1) * at.y
                  + lrelu(xa.z + xb.z + m2) * at.z
                  + lrelu(xa.w + xb.w + m3) * at.w;
        sum += __shfl_xor_sync(0xffffffffu, sum, 1);
        sum += __shfl_xor_sync(0xffffffffu, sum, 2);

        float pv = expf(sum);                 // softmax is shift-invariant
        if ((lane & 3) == 0)
            atomicAdd(&g_denom[(size_t)d * NH + h], pv);
        xa.x *= pv; xa.y *= pv; xa.z *= pv; xa.w *= pv;
        atomicAdd((float4*)&g_agg[(size_t)d * HD + c], xa);
    }
}

// x = relu(LN(agg/denom + bias_o)) + x ; re-zeroes agg/denom for next layer.
__global__ void __launch_bounds__(256)
node_finish_kernel(const float* __restrict__ bo_l,
                   const float* __restrict__ lg_l,
                   const float* __restrict__ lb_l,
                   float* __restrict__ x) {
    int n = blockIdx.x * 8 + (threadIdx.x >> 5);
    if (n >= NN) return;
    int lane = threadIdx.x & 31;
    int h = lane >> 2;

    float den = g_denom[(size_t)n * NH + h] + 1e-16f;
    float rden = 1.f / den;

    float4 v  = *(const float4*)&g_agg[(size_t)n * HD + lane * 4];
    float4 bo = *(const float4*)&bo_l[lane * 4];
    v.x = fmaf(v.x, rden, bo.x); v.y = fmaf(v.y, rden, bo.y);
    v.z = fmaf(v.z, rden, bo.z); v.w = fmaf(v.w, rden, bo.w);

    *(float4*)&g_agg[(size_t)n * HD + lane * 4] = make_float4(0.f, 0.f, 0.f, 0.f);
    if ((lane & 3) == 0) g_denom[(size_t)n * NH + h] = 0.f;

    float s  = v.x + v.y + v.z + v.w;
    float sq = v.x * v.x + v.y * v.y + v.z * v.z + v.w * v.w;
    #pragma unroll
    for (int o = 16; o > 0; o >>= 1) {
        s  += __shfl_xor_sync(0xffffffffu, s,  o);
        sq += __shfl_xor_sync(0xffffffffu, sq, o);
    }
    float mu  = s * (1.f / HD);
    float var = sq * (1.f / HD) - mu * mu;
    float inv = rsqrtf(var + 1e-5f);

    float4 g  = *(const float4*)&lg_l[lane * 4];
    float4 bb = *(const float4*)&lb_l[lane * 4];
    float4 xi = *(const float4*)&x[(size_t)n * HD + lane * 4];

    float4 o;
    o.x = fmaxf(g.x * (v.x - mu) * inv + bb.x, 0.f) + xi.x;
    o.y = fmaxf(g.y * (v.y - mu) * inv + bb.y, 0.f) + xi.y;
    o.z = fmaxf(g.z * (v.z - mu) * inv + bb.z, 0.f) + xi.z;
    o.w = fmaxf(g.w * (v.w - mu) * inv + bb.w, 0.f) + xi.w;
    *(float4*)&x[(size_t)n * HD + lane * 4] = o;
}

// ---------------- host ------------------------------------------------------
extern "C" void kernel_launch(void* const* d_in, const int* in_sizes, int n_in,
                              void* d_out, int out_size) {
    const float* x_in   = (const float*)d_in[0];
    const int*   eidx   = (const int*)  d_in[2];
    const float* eattr  = (const float*)d_in[3];
    const float* Wt     = (const float*)d_in[4];
    const float* bt     = (const float*)d_in[5];
    const float* Wl     = (const float*)d_in[6];
    const float* bl     = (const float*)d_in[7];
    const float* Wr     = (const float*)d_in[8];
    const float* br     = (const float*)d_in[9];
    const float* We     = (const float*)d_in[10];
    const float* att    = (const float*)d_in[11];
    const float* bias_o = (const float*)d_in[12];
    const float* ln_g   = (const float*)d_in[13];
    const float* ln_b   = (const float*)d_in[14];
    float* x = (float*)d_out;

    const int* src = eidx;
    const int* dst = eidx + EE;

    float *p_Wf, *p_bf;
    cudaGetSymbolAddress((void**)&p_Wf, g_Wf);
    cudaGetSymbolAddress((void**)&p_bf, g_bf);

    cudaMemcpyAsync(x, x_in, (size_t)NN * HD * sizeof(float),
                    cudaMemcpyDeviceToDevice);

    fusew_kernel<<<LL, HD>>>(Wt, bt, We);
    zero_kernel<<<(NN * HD + 255) / 256, 256>>>();

    for (int l = 0; l < LL; l++) {
        node_gemm_kernel<<<NN / 16 + 1, 256>>>(x,
                                          Wl + (size_t)l * HD * HD, bl + l * HD,
                                          Wr + (size_t)l * HD * HD, br + l * HD);
        edge_p_kernel<<<EE / 64, 512>>>(src, dst, eattr, att + l * NH * CC,
                                        p_Wf + (size_t)l * EFD * HD,
                                        p_bf + (size_t)l * HD);
        node_finish_kernel<<<NN / 8 + 1, 256>>>(bias_o + l * HD,
                                                ln_g + l * HD,
                                                ln_b + l * HD, x);
    }
}

// round 11
// speedup vs baseline: 10.0856x; 1.0659x over previous
#include <cuda_runtime.h>
#include <math.h>

#define NN   50000
#define EE   640000
#define HD   128
#define NH   8
#define CC   16
#define LL   3
#define EFD  16

typedef unsigned long long ull;

// ---------------- scratch (static device globals) ---------------------------
__device__ __align__(256) float g_xl   [(size_t)NN * HD];
__device__ __align__(256) float g_xr   [(size_t)NN * HD];
__device__ __align__(256) float g_denom[(size_t)NN * NH];
__device__ __align__(256) float g_agg  [(size_t)NN * HD];
__device__ __align__(256) float g_Wf   [LL][EFD * HD];   // Wt @ We[l]
__device__ __align__(256) float g_bf   [LL][HD];         // bt @ We[l]

// ---------------- helpers ---------------------------------------------------
__device__ __forceinline__ ull bcast2(float x) {
    ull r; asm("mov.b64 %0, {%1, %1};" : "=l"(r) : "f"(x)); return r;
}
__device__ __forceinline__ ull pack2(float lo, float hi) {
    ull r; asm("mov.b64 %0, {%1, %2};" : "=l"(r) : "f"(lo), "f"(hi)); return r;
}
__device__ __forceinline__ void fma2(ull& acc, ull a, ull b) {
    asm("fma.rn.f32x2 %0, %1, %2, %0;" : "+l"(acc) : "l"(a), "l"(b));
}
__device__ __forceinline__ void unpack2(ull v, float& lo, float& hi) {
    asm("mov.b64 {%0, %1}, %2;" : "=f"(lo), "=f"(hi) : "l"(v));
}
__device__ __forceinline__ float lrelu(float x) { return fmaxf(x, 0.2f * x); }

// ---------------- kernels ---------------------------------------------------

// Fold edge_transform into each layer's lin_edge:
//   Wf[l] = Wt @ We[l]  [16,128];  bf[l] = bt @ We[l]  [128]
__global__ void fusew_kernel(const float* __restrict__ Wt,
                             const float* __restrict__ bt,
                             const float* __restrict__ We) {
    int l = blockIdx.x;
    int j = threadIdx.x;
    const float* We_l = We + (size_t)l * HD * HD;
    float b = 0.f;
    for (int m = 0; m < HD; m++) b = fmaf(bt[m], We_l[m * HD + j], b);
    g_bf[l][j] = b;
    #pragma unroll
    for (int k = 0; k < EFD; k++) {
        float s = 0.f;
        for (int m = 0; m < HD; m++) s = fmaf(Wt[k * HD + m], We_l[m * HD + j], s);
        g_Wf[l][k * HD + j] = s;
    }
}

// xl = x@Wl + bl, xr = x@Wr + br in one launch. 32 rows/block, 256 threads
// (half does Wl, half Wr). Per-thread: 16 rows x 2 cols.
__global__ void __launch_bounds__(256)
node_gemm_kernel(const float* __restrict__ x,
                 const float* __restrict__ Wl_l, const float* __restrict__ bl_l,
                 const float* __restrict__ Wr_l, const float* __restrict__ br_l) {
    __shared__ float AsT[HD][32];        // [k][row]
    int row0 = blockIdx.x * 32;
    for (int i = threadIdx.x; i < 32 * HD; i += 256) {
        int r = i >> 7, c = i & 127;
        AsT[c][r] = (row0 + r < NN) ? x[(size_t)(row0 + r) * HD + c] : 0.f;
    }
    __syncthreads();

    int half = threadIdx.x >> 7;         // 0 -> lin_l, 1 -> lin_r
    int t    = threadIdx.x & 127;
    const float* W    = half ? Wr_l : Wl_l;
    const float* bias = half ? br_l : bl_l;
    float* C          = half ? g_xr : g_xl;

    int p  = t & 63;                     // column pair (2p, 2p+1)
    int rb = (t >> 6) * 16;              // rows rb..rb+15

    ull acc[16];
    #pragma unroll
    for (int i = 0; i < 16; i++) acc[i] = 0ull;
    const ull* W2 = (const ull*)W;

    #pragma unroll 4
    for (int k = 0; k < HD; k++) {
        ull w = W2[k * 64 + p];
        float wlo, whi; unpack2(w, wlo, whi);
        ull wl2 = bcast2(wlo), wh2 = bcast2(whi);
        #pragma unroll
        for (int q = 0; q < 4; q++) {
            float4 a = *(const float4*)&AsT[k][rb + 4 * q];
            ull aA = pack2(a.x, a.y), aB = pack2(a.z, a.w);
            fma2(acc[2 * q],     aA, wl2);
            fma2(acc[2 * q + 1], aB, wl2);
            fma2(acc[8 + 2 * q],     aA, wh2);
            fma2(acc[8 + 2 * q + 1], aB, wh2);
        }
    }
    float blo = bias[2 * p], bhi = bias[2 * p + 1];
    #pragma unroll
    for (int g = 0; g < 8; g++) {
        int r0 = row0 + rb + 2 * g;
        float f0, f1;
        unpack2(acc[g], f0, f1);
        if (r0 < NN)     C[(size_t)r0 * HD + 2 * p]       = f0 + blo;
        if (r0 + 1 < NN) C[(size_t)(r0 + 1) * HD + 2 * p] = f1 + blo;
        unpack2(acc[8 + g], f0, f1);
        if (r0 < NN)     C[(size_t)r0 * HD + 2 * p + 1]       = f0 + bhi;
        if (r0 + 1 < NN) C[(size_t)(r0 + 1) * HD + 2 * p + 1] = f1 + bhi;
    }
}

// one-time zero of the accumulators (before layer 0)
__global__ void zero_kernel() {
    int i = blockIdx.x * blockDim.x + threadIdx.x;
    if (i < NN * HD) g_agg[i] = 0.f;
    if (i < NN * NH) g_denom[i] = 0.f;
}

// Fused edge pass, 4 edges per warp: Wf smem row loaded once per k-step and
// shared across 4 edges via static-index register shuffles of the ea scalars.
// __launch_bounds__(512,3): cap regs at 42 so 3 blocks/SM fit (R10 occ=44%).
__global__ void __launch_bounds__(512, 3)
edge_p_kernel(const int* __restrict__ src, const int* __restrict__ dst,
              const float* __restrict__ eattr, const float* __restrict__ att_l,
              const float* __restrict__ Wf_l, const float* __restrict__ bf_l) {
    __shared__ float Wfs[EFD * HD];
    __shared__ float bfs[HD];
    __shared__ float atts[NH * CC];
    for (int i = threadIdx.x; i < EFD * HD; i += 512) Wfs[i] = Wf_l[i];
    if (threadIdx.x < HD) {
        bfs[threadIdx.x]  = bf_l[threadIdx.x];
        atts[threadIdx.x] = att_l[threadIdx.x];
    }
    __syncthreads();

    int warp = threadIdx.x >> 5;
    int lane = threadIdx.x & 31;
    int e0   = blockIdx.x * 64 + warp * 4;      // 4 consecutive edges
    int h = lane >> 2;
    int c = lane * 4;

    // 4 edges x 16 attrs = 64 floats, 2 per lane (coalesced 128B loads)
    float ea_a = eattr[(size_t)e0 * EFD + lane];        // values 0..31
    float ea_b = eattr[(size_t)e0 * EFD + 32 + lane];   // values 32..63

    // em accumulators: em[g][0] = channels c,c+1 ; em[g][1] = c+2,c+3
    ull em[4][2];
    {
        ulonglong2 bv = *(const ulonglong2*)&bfs[c];
        #pragma unroll
        for (int g = 0; g < 4; g++) { em[g][0] = bv.x; em[g][1] = bv.y; }
    }

    #pragma unroll
    for (int k = 0; k < EFD; k++) {
        float4 w = *(const float4*)&Wfs[k * HD + c];    // shared by 4 edges
        ull wxy = pack2(w.x, w.y), wzw = pack2(w.z, w.w);
        #pragma unroll
        for (int g = 0; g < 4; g++) {
            int v = g * EFD + k;                        // compile-time
            float a = __shfl_sync(0xffffffffu,
                                  (v < 32) ? ea_a : ea_b, v & 31);
            ull a2 = bcast2(a);
            fma2(em[g][0], a2, wxy);
            fma2(em[g][1], a2, wzw);
        }
    }

    int4 s4 = *(const int4*)&src[e0];
    int4 d4 = *(const int4*)&dst[e0];
    int ss[4] = {s4.x, s4.y, s4.z, s4.w};
    int dd[4] = {d4.x, d4.y, d4.z, d4.w};

    float4 at = *(const float4*)&atts[h * CC + (lane & 3) * 4];

    #pragma unroll
    for (int g = 0; g < 4; g++) {
        int s = ss[g], d = dd[g];
        float4 xa = *(const float4*)&g_xl[(size_t)s * HD + c];
        float4 xb = *(const float4*)&g_xr[(size_t)d * HD + c];
        float m0, m1, m2, m3;
        unpack2(em[g][0], m0, m1);
        unpack2(em[g][1], m2, m3);

        float sum = lrelu(xa.x + xb.x + m0) * at.x
                  + lrelu(xa.y + xb.y + m1) * at.y
                  + lrelu(xa.z + xb.z + m2) * at.z
                  + lrelu(xa.w + xb.w + m3) * at.w;
        sum += __shfl_xor_sync(0xffffffffu, sum, 1);
        sum += __shfl_xor_sync(0xffffffffu, sum, 2);

        float pv = expf(sum);                 // softmax is shift-invariant
        if ((lane & 3) == 0)
            atomicAdd(&g_denom[(size_t)d * NH + h], pv);
        xa.x *= pv; xa.y *= pv; xa.z *= pv; xa.w *= pv;
        atomicAdd((float4*)&g_agg[(size_t)d * HD + c], xa);
    }
}

// x = relu(LN(agg/denom + bias_o)) + x ; re-zeroes agg/denom for next layer.
__global__ void __launch_bounds__(256)
node_finish_kernel(const float* __restrict__ bo_l,
                   const float* __restrict__ lg_l,
                   const float* __restrict__ lb_l,
                   float* __restrict__ x) {
    int n = blockIdx.x * 8 + (threadIdx.x >> 5);
    if (n >= NN) return;
    int lane = threadIdx.x & 31;
    int h = lane >> 2;

    float den = g_denom[(size_t)n * NH + h] + 1e-16f;
    float rden = 1.f / den;

    float4 v  = *(const float4*)&g_agg[(size_t)n * HD + lane * 4];
    float4 bo = *(const float4*)&bo_l[lane * 4];
    v.x = fmaf(v.x, rden, bo.x); v.y = fmaf(v.y, rden, bo.y);
    v.z = fmaf(v.z, rden, bo.z); v.w = fmaf(v.w, rden, bo.w);

    *(float4*)&g_agg[(size_t)n * HD + lane * 4] = make_float4(0.f, 0.f, 0.f, 0.f);
    if ((lane & 3) == 0) g_denom[(size_t)n * NH + h] = 0.f;

    float s  = v.x + v.y + v.z + v.w;
    float sq = v.x * v.x + v.y * v.y + v.z * v.z + v.w * v.w;
    #pragma unroll
    for (int o = 16; o > 0; o >>= 1) {
        s  += __shfl_xor_sync(0xffffffffu, s,  o);
        sq += __shfl_xor_sync(0xffffffffu, sq, o);
    }
    float mu  = s * (1.f / HD);
    float var = sq * (1.f / HD) - mu * mu;
    float inv = rsqrtf(var + 1e-5f);

    float4 g  = *(const float4*)&lg_l[lane * 4];
    float4 bb = *(const float4*)&lb_l[lane * 4];
    float4 xi = *(const float4*)&x[(size_t)n * HD + lane * 4];

    float4 o;
    o.x = fmaxf(g.x * (v.x - mu) * inv + bb.x, 0.f) + xi.x;
    o.y = fmaxf(g.y * (v.y - mu) * inv + bb.y, 0.f) + xi.y;
    o.z = fmaxf(g.z * (v.z - mu) * inv + bb.z, 0.f) + xi.z;
    o.w = fmaxf(g.w * (v.w - mu) * inv + bb.w, 0.f) + xi.w;
    *(float4*)&x[(size_t)n * HD + lane * 4] = o;
}

// ---------------- host ------------------------------------------------------
extern "C" void kernel_launch(void* const* d_in, const int* in_sizes, int n_in,
                              void* d_out, int out_size) {
    const float* x_in   = (const float*)d_in[0];
    const int*   eidx   = (const int*)  d_in[2];
    const float* eattr  = (const float*)d_in[3];
    const float* Wt     = (const float*)d_in[4];
    const float* bt     = (const float*)d_in[5];
    const float* Wl     = (const float*)d_in[6];
    const float* bl     = (const float*)d_in[7];
    const float* Wr     = (const float*)d_in[8];
    const float* br     = (const float*)d_in[9];
    const float* We     = (const float*)d_in[10];
    const float* att    = (const float*)d_in[11];
    const float* bias_o = (const float*)d_in[12];
    const float* ln_g   = (const float*)d_in[13];
    const float* ln_b   = (const float*)d_in[14];
    float* x = (float*)d_out;

    const int* src = eidx;
    const int* dst = eidx + EE;

    float *p_Wf, *p_bf;
    cudaGetSymbolAddress((void**)&p_Wf, g_Wf);
    cudaGetSymbolAddress((void**)&p_bf, g_bf);

    cudaMemcpyAsync(x, x_in, (size_t)NN * HD * sizeof(float),
                    cudaMemcpyDeviceToDevice);

    fusew_kernel<<<LL, HD>>>(Wt, bt, We);
    zero_kernel<<<(NN * HD + 255) / 256, 256>>>();

    for (int l = 0; l < LL; l++) {
        node_gemm_kernel<<<(NN + 31) / 32, 256>>>(x,
                                          Wl + (size_t)l * HD * HD, bl + l * HD,
                                          Wr + (size_t)l * HD * HD, br + l * HD);
        edge_p_kernel<<<EE / 64, 512>>>(src, dst, eattr, att + l * NH * CC,
                                        p_Wf + (size_t)l * EFD * HD,
                                        p_bf + (size_t)l * HD);
        node_finish_kernel<<<NN / 8 + 1, 256>>>(bias_o + l * HD,
                                                ln_g + l * HD,
                                                ln_b + l * HD, x);
    }
}

// round 14
// speedup vs baseline: 11.0571x; 1.0963x over previous
#include <cuda_runtime.h>
#include <math.h>

#define NN   50000
#define EE   640000
#define HD   128
#define NH   8
#define CC   16
#define LL   3
#define EFD  16

typedef unsigned long long ull;

// ---------------- scratch (static device globals) ---------------------------
__device__ __align__(256) float g_xl   [(size_t)NN * HD];
__device__ __align__(256) float g_xr   [(size_t)NN * HD];
__device__ __align__(256) float g_denom[(size_t)NN * NH];
__device__ __align__(256) float g_agg  [(size_t)NN * HD];
__device__ __align__(256) float g_Wf   [LL][EFD * HD];   // Wt @ We[l]
__device__ __align__(256) float g_bf   [LL][HD];         // bt @ We[l]

// ---------------- helpers ---------------------------------------------------
__device__ __forceinline__ ull bcast2(float x) {
    ull r; asm("mov.b64 %0, {%1, %1};" : "=l"(r) : "f"(x)); return r;
}
__device__ __forceinline__ ull pack2(float lo, float hi) {
    ull r; asm("mov.b64 %0, {%1, %2};" : "=l"(r) : "f"(lo), "f"(hi)); return r;
}
__device__ __forceinline__ void fma2(ull& acc, ull a, ull b) {
    asm("fma.rn.f32x2 %0, %1, %2, %0;" : "+l"(acc) : "l"(a), "l"(b));
}
__device__ __forceinline__ void unpack2(ull v, float& lo, float& hi) {
    asm("mov.b64 {%0, %1}, %2;" : "=f"(lo), "=f"(hi) : "l"(v));
}
__device__ __forceinline__ float lrelu(float x) { return fmaxf(x, 0.2f * x); }

// ---------------- kernels ---------------------------------------------------

// Fold edge_transform into each layer's lin_edge:
//   Wf[l] = Wt @ We[l]  [16,128];  bf[l] = bt @ We[l]  [128]
__global__ void fusew_kernel(const float* __restrict__ Wt,
                             const float* __restrict__ bt,
                             const float* __restrict__ We) {
    int l = blockIdx.x;
    int j = threadIdx.x;
    const float* We_l = We + (size_t)l * HD * HD;
    float b = 0.f;
    for (int m = 0; m < HD; m++) b = fmaf(bt[m], We_l[m * HD + j], b);
    g_bf[l][j] = b;
    #pragma unroll
    for (int k = 0; k < EFD; k++) {
        float s = 0.f;
        for (int m = 0; m < HD; m++) s = fmaf(Wt[k * HD + m], We_l[m * HD + j], s);
        g_Wf[l][k * HD + j] = s;
    }
}

// xl = x@Wl + bl, xr = x@Wr + br in one launch. 32 rows/block, 256 threads
// (half does Wl, half Wr). Per-thread: 16 rows x 2 cols.
__global__ void __launch_bounds__(256)
node_gemm_kernel(const float* __restrict__ x,
                 const float* __restrict__ Wl_l, const float* __restrict__ bl_l,
                 const float* __restrict__ Wr_l, const float* __restrict__ br_l) {
    __shared__ float AsT[HD][32];        // [k][row]
    int row0 = blockIdx.x * 32;
    for (int i = threadIdx.x; i < 32 * HD; i += 256) {
        int r = i >> 7, c = i & 127;
        AsT[c][r] = (row0 + r < NN) ? x[(size_t)(row0 + r) * HD + c] : 0.f;
    }
    __syncthreads();

    int half = threadIdx.x >> 7;         // 0 -> lin_l, 1 -> lin_r
    int t    = threadIdx.x & 127;
    const float* W    = half ? Wr_l : Wl_l;
    const float* bias = half ? br_l : bl_l;
    float* C          = half ? g_xr : g_xl;

    int p  = t & 63;                     // column pair (2p, 2p+1)
    int rb = (t >> 6) * 16;              // rows rb..rb+15

    ull acc[16];
    #pragma unroll
    for (int i = 0; i < 16; i++) acc[i] = 0ull;
    const ull* W2 = (const ull*)W;

    #pragma unroll 4
    for (int k = 0; k < HD; k++) {
        ull w = W2[k * 64 + p];
        float wlo, whi; unpack2(w, wlo, whi);
        ull wl2 = bcast2(wlo), wh2 = bcast2(whi);
        #pragma unroll
        for (int q = 0; q < 4; q++) {
            float4 a = *(const float4*)&AsT[k][rb + 4 * q];
            ull aA = pack2(a.x, a.y), aB = pack2(a.z, a.w);
            fma2(acc[2 * q],     aA, wl2);
            fma2(acc[2 * q + 1], aB, wl2);
            fma2(acc[8 + 2 * q],     aA, wh2);
            fma2(acc[8 + 2 * q + 1], aB, wh2);
        }
    }
    float blo = bias[2 * p], bhi = bias[2 * p + 1];
    #pragma unroll
    for (int g = 0; g < 8; g++) {
        int r0 = row0 + rb + 2 * g;
        float f0, f1;
        unpack2(acc[g], f0, f1);
        if (r0 < NN)     C[(size_t)r0 * HD + 2 * p]       = f0 + blo;
        if (r0 + 1 < NN) C[(size_t)(r0 + 1) * HD + 2 * p] = f1 + blo;
        unpack2(acc[8 + g], f0, f1);
        if (r0 < NN)     C[(size_t)r0 * HD + 2 * p + 1]       = f0 + bhi;
        if (r0 + 1 < NN) C[(size_t)(r0 + 1) * HD + 2 * p + 1] = f1 + bhi;
    }
}

// one-time zero of the accumulators (before layer 0)
__global__ void zero_kernel() {
    int i = blockIdx.x * blockDim.x + threadIdx.x;
    if (i < NN * HD) g_agg[i] = 0.f;
    if (i < NN * NH) g_denom[i] = 0.f;
}

// Fused edge pass, 8 edges per warp: Wf smem row loaded once per k-step and
// shared across 8 edges via static-index register shuffles of the ea scalars.
// 64-reg cap via (512,2): 2x512 threads = 32 warps/SM fills the reg file.
__global__ void __launch_bounds__(512, 2)
edge_p_kernel(const int* __restrict__ src, const int* __restrict__ dst,
              const float* __restrict__ eattr, const float* __restrict__ att_l,
              const float* __restrict__ Wf_l, const float* __restrict__ bf_l) {
    __shared__ float Wfs[EFD * HD];
    __shared__ float bfs[HD];
    __shared__ float atts[NH * CC];
    for (int i = threadIdx.x; i < EFD * HD; i += 512) Wfs[i] = Wf_l[i];
    if (threadIdx.x < HD) {
        bfs[threadIdx.x]  = bf_l[threadIdx.x];
        atts[threadIdx.x] = att_l[threadIdx.x];
    }
    __syncthreads();

    int warp = threadIdx.x >> 5;
    int lane = threadIdx.x & 31;
    int e0   = blockIdx.x * 128 + warp * 8;     // 8 consecutive edges
    int h = lane >> 2;
    int c = lane * 4;

    // 8 edges x 16 attrs = 128 floats, 4 per lane (coalesced 128B loads)
    float ea_r[4];
    #pragma unroll
    for (int i = 0; i < 4; i++)
        ea_r[i] = eattr[(size_t)e0 * EFD + i * 32 + lane];

    // em accumulators: em[g][0] = channels c,c+1 ; em[g][1] = c+2,c+3
    ull em[8][2];
    {
        ulonglong2 bv = *(const ulonglong2*)&bfs[c];
        #pragma unroll
        for (int g = 0; g < 8; g++) { em[g][0] = bv.x; em[g][1] = bv.y; }
    }

    #pragma unroll
    for (int k = 0; k < EFD; k++) {
        float4 w = *(const float4*)&Wfs[k * HD + c];    // shared by 8 edges
        ull wxy = pack2(w.x, w.y), wzw = pack2(w.z, w.w);
        #pragma unroll
        for (int g = 0; g < 8; g++) {
            int v = g * EFD + k;                        // compile-time
            float a = __shfl_sync(0xffffffffu, ea_r[v >> 5], v & 31);
            ull a2 = bcast2(a);
            fma2(em[g][0], a2, wxy);
            fma2(em[g][1], a2, wzw);
        }
    }

    int4 sa = *(const int4*)&src[e0];
    int4 sb = *(const int4*)&src[e0 + 4];
    int4 da = *(const int4*)&dst[e0];
    int4 db = *(const int4*)&dst[e0 + 4];
    int ss[8] = {sa.x, sa.y, sa.z, sa.w, sb.x, sb.y, sb.z, sb.w};
    int dd[8] = {da.x, da.y, da.z, da.w, db.x, db.y, db.z, db.w};

    float4 at = *(const float4*)&atts[h * CC + (lane & 3) * 4];

    #pragma unroll
    for (int g = 0; g < 8; g++) {
        int s = ss[g], d = dd[g];
        float4 xa = *(const float4*)&g_xl[(size_t)s * HD + c];
        float4 xb = *(const float4*)&g_xr[(size_t)d * HD + c];
        float m0, m1, m2, m3;
        unpack2(em[g][0], m0, m1);
        unpack2(em[g][1], m2, m3);

        float sum = lrelu(xa.x + xb.x + m0) * at.x
                  + lrelu(xa.y + xb.y + m1) * at.y
                  + lrelu(xa.z + xb.z + m2) * at.z
                  + lrelu(xa.w + xb.w + m3) * at.w;
        sum += __shfl_xor_sync(0xffffffffu, sum, 1);
        sum += __shfl_xor_sync(0xffffffffu, sum, 2);

        float pv = expf(sum);                 // softmax is shift-invariant
        if ((lane & 3) == 0)
            atomicAdd(&g_denom[(size_t)d * NH + h], pv);
        xa.x *= pv; xa.y *= pv; xa.z *= pv; xa.w *= pv;
        atomicAdd((float4*)&g_agg[(size_t)d * HD + c], xa);
    }
}

// x_out = relu(LN(agg/denom + bias_o)) + x_res ; re-zeroes agg/denom.
__global__ void __launch_bounds__(256)
node_finish_kernel(const float* __restrict__ bo_l,
                   const float* __restrict__ lg_l,
                   const float* __restrict__ lb_l,
                   const float* __restrict__ x_res,
                   float* __restrict__ x_out) {
    int n = blockIdx.x * 8 + (threadIdx.x >> 5);
    if (n >= NN) return;
    int lane = threadIdx.x & 31;
    int h = lane >> 2;

    float den = g_denom[(size_t)n * NH + h] + 1e-16f;
    float rden = 1.f / den;

    float4 v  = *(const float4*)&g_agg[(size_t)n * HD + lane * 4];
    float4 bo = *(const float4*)&bo_l[lane * 4];
    v.x = fmaf(v.x, rden, bo.x); v.y = fmaf(v.y, rden, bo.y);
    v.z = fmaf(v.z, rden, bo.z); v.w = fmaf(v.w, rden, bo.w);

    *(float4*)&g_agg[(size_t)n * HD + lane * 4] = make_float4(0.f, 0.f, 0.f, 0.f);
    if ((lane & 3) == 0) g_denom[(size_t)n * NH + h] = 0.f;

    float s  = v.x + v.y + v.z + v.w;
    float sq = v.x * v.x + v.y * v.y + v.z * v.z + v.w * v.w;
    #pragma unroll
    for (int o = 16; o > 0; o >>= 1) {
        s  += __shfl_xor_sync(0xffffffffu, s,  o);
        sq += __shfl_xor_sync(0xffffffffu, sq, o);
    }
    float mu  = s * (1.f / HD);
    float var = sq * (1.f / HD) - mu * mu;
    float inv = rsqrtf(var + 1e-5f);

    float4 g  = *(const float4*)&lg_l[lane * 4];
    float4 bb = *(const float4*)&lb_l[lane * 4];
    float4 xi = *(const float4*)&x_res[(size_t)n * HD + lane * 4];

    float4 o;
    o.x = fmaxf(g.x * (v.x - mu) * inv + bb.x, 0.f) + xi.x;
    o.y = fmaxf(g.y * (v.y - mu) * inv + bb.y, 0.f) + xi.y;
    o.z = fmaxf(g.z * (v.z - mu) * inv + bb.z, 0.f) + xi.z;
    o.w = fmaxf(g.w * (v.w - mu) * inv + bb.w, 0.f) + xi.w;
    *(float4*)&x_out[(size_t)n * HD + lane * 4] = o;
}

// ---------------- host ------------------------------------------------------
extern "C" void kernel_launch(void* const* d_in, const int* in_sizes, int n_in,
                              void* d_out, int out_size) {
    const float* x_in   = (const float*)d_in[0];
    const int*   eidx   = (const int*)  d_in[2];
    const float* eattr  = (const float*)d_in[3];
    const float* Wt     = (const float*)d_in[4];
    const float* bt     = (const float*)d_in[5];
    const float* Wl     = (const float*)d_in[6];
    const float* bl     = (const float*)d_in[7];
    const float* Wr     = (const float*)d_in[8];
    const float* br     = (const float*)d_in[9];
    const float* We     = (const float*)d_in[10];
    const float* att    = (const float*)d_in[11];
    const float* bias_o = (const float*)d_in[12];
    const float* ln_g   = (const float*)d_in[13];
    const float* ln_b   = (const float*)d_in[14];
    float* x = (float*)d_out;

    const int* src = eidx;
    const int* dst = eidx + EE;

    float *p_Wf, *p_bf;
    cudaGetSymbolAddress((void**)&p_Wf, g_Wf);
    cudaGetSymbolAddress((void**)&p_bf, g_bf);

    fusew_kernel<<<LL, HD>>>(Wt, bt, We);
    zero_kernel<<<(NN * HD + 255) / 256, 256>>>();

    for (int l = 0; l < LL; l++) {
        const float* xin = (l == 0) ? x_in : x;   // layer 0 reads input directly
        node_gemm_kernel<<<(NN + 31) / 32, 256>>>(xin,
                                          Wl + (size_t)l * HD * HD, bl + l * HD,
                                          Wr + (size_t)l * HD * HD, br + l * HD);
        edge_p_kernel<<<EE / 128, 512>>>(src, dst, eattr, att + l * NH * CC,
                                         p_Wf + (size_t)l * EFD * HD,
                                         p_bf + (size_t)l * HD);
        node_finish_kernel<<<NN / 8 + 1, 256>>>(bias_o + l * HD,
                                                ln_g + l * HD,
                                                ln_b + l * HD, xin, x);
    }
}